// round 13
// baseline (speedup 1.0000x reference)
#include <cuda_runtime.h>
#include <math.h>

#define BATCH 4
#define SEQ 2048
#define DMODEL 768
#define NHEAD 12
#define HDIM 64
#define M_ROWS (BATCH*SEQ)   // 8192

// Scratch (device globals: allocation is forbidden)
__device__ float g_q[(size_t)BATCH*NHEAD*SEQ*HDIM];
__device__ float g_k[(size_t)BATCH*NHEAD*SEQ*HDIM];
__device__ float g_v[(size_t)BATCH*NHEAD*SEQ*HDIM];
__device__ float g_attn[(size_t)M_ROWS*DMODEL];

// ---------------------------------------------------------------------------
// GEMM: C[m,n] = sum_k A[m,k]*W[n,k] + bias[n]   (torch Linear: x @ W^T + b)
// BM=128, BN=64, BK=16, 256 threads, 8x4 outputs/thread (tx: n, ty: m).
// MODE 0: A = host-passed x; scatter into [b,h,s,hd] (sel picks q/k/v)
// MODE 1: A = g_attn resolved IN DEVICE CODE (a __device__ symbol passed from
//         host decays to the host shadow; GB300 ATS reads it as zeros).
// ---------------------------------------------------------------------------
template<int MODE>
__global__ void __launch_bounds__(256) gemm_kernel(const float* __restrict__ A,
                                                   const float* __restrict__ W,
                                                   const float* __restrict__ bias,
                                                   float* __restrict__ Cq, int sel)
{
    __shared__ __align__(16) float As[16][136];   // [k][m], 128 m
    __shared__ __align__(16) float Bs[16][68];    // [k][n], 64 n
    const int tid = threadIdx.x;
    const int tx = tid & 15, ty = tid >> 4;
    const int m0 = blockIdx.y * 128, n0 = blockIdx.x * 64;

    const int ar = tid >> 1, ac = (tid & 1) * 8;  // A loader: row, k-chunk
    const int br = tid >> 2, bc = (tid & 3) * 4;  // B loader

    const float* Asrc = (MODE == 1) ? (const float*)g_attn : A;
    const float* Ap = Asrc + (size_t)(m0 + ar) * DMODEL + ac;
    const float* Wp = W    + (size_t)(n0 + br) * DMODEL + bc;

    float acc[8][4] = {};

    for (int k0 = 0; k0 < DMODEL; k0 += 16) {
        float4 a0 = *(const float4*)(Ap + k0);
        float4 a1 = *(const float4*)(Ap + k0 + 4);
        float4 bv = *(const float4*)(Wp + k0);
        __syncthreads();
        As[ac+0][ar]=a0.x; As[ac+1][ar]=a0.y; As[ac+2][ar]=a0.z; As[ac+3][ar]=a0.w;
        As[ac+4][ar]=a1.x; As[ac+5][ar]=a1.y; As[ac+6][ar]=a1.z; As[ac+7][ar]=a1.w;
        Bs[bc+0][br]=bv.x; Bs[bc+1][br]=bv.y; Bs[bc+2][br]=bv.z; Bs[bc+3][br]=bv.w;
        __syncthreads();
        #pragma unroll
        for (int kk = 0; kk < 16; kk++) {
            float4 x0 = *(const float4*)&As[kk][ty*8];
            float4 x1 = *(const float4*)&As[kk][ty*8+4];
            float4 y  = *(const float4*)&Bs[kk][tx*4];
            float ar8[8] = {x0.x,x0.y,x0.z,x0.w, x1.x,x1.y,x1.z,x1.w};
            float br4[4] = {y.x, y.y, y.z, y.w};
            #pragma unroll
            for (int i = 0; i < 8; i++)
                #pragma unroll
                for (int j = 0; j < 4; j++)
                    acc[i][j] += ar8[i] * br4[j];
        }
    }

    float* out = Cq;
    if (MODE == 0) out = (sel == 0) ? g_q : (sel == 1) ? g_k : g_v;

    #pragma unroll
    for (int i = 0; i < 8; i++) {
        int m = m0 + ty*8 + i;
        #pragma unroll
        for (int j = 0; j < 4; j++) {
            int n = n0 + tx*4 + j;
            float v = acc[i][j] + bias[n];
            if (MODE == 0) {
                int b = m >> 11, s = m & 2047;
                int h = n >> 6,  hd = n & 63;
                out[(((size_t)(b*NHEAD + h))*SEQ + s)*HDIM + hd] = v;
            } else {
                out[(size_t)m*DMODEL + n] = v;
            }
        }
    }
}

// ---------------------------------------------------------------------------
// Flash attention, register-blocked, Q-tile 128 x K-tile 64.
// grid (SEQ/128, BATCH*NHEAD), 256 threads; thread owns 8 q-rows (ty*8+i)
// x 4 key-cols / 4 out-dims (tx*4+j). Rank-1 updates: 3x LDS.128 -> 32 FMA.
// Q staged d-major once per block; K d-major per tile; P has a DEDICATED
// buffer (no reuse) with a full barrier before PV; V row-major.
// Row softmax reduces across the 16 tx lanes (lane bits 0-3) via shfl_xor.
// Dynamic shared: QS[64][136] KS[64][68] VS[64][68] PS[64][136] = 102 KB.
// ---------------------------------------------------------------------------
#define QS(d,m)  sm[(d)*136 + (m)]
#define KS(d,n)  sm[8704  + (d)*68  + (n)]
#define VS(j,e)  sm[13056 + (j)*68  + (e)]
#define PS(j,m)  sm[17408 + (j)*136 + (m)]
#define ATTN_SMEM (26112*4)

__global__ void __launch_bounds__(256, 2) attn_kernel()
{
    extern __shared__ __align__(16) float sm[];

    const int tid = threadIdx.x;
    const int tx  = tid & 15, ty = tid >> 4;
    const int bh  = blockIdx.y;
    const int q0  = blockIdx.x * 128;
    const int lr  = tid >> 2, lc = (tid & 3) * 16;   // K/V loader
    const int qr  = tid >> 1, qc = (tid & 1) * 32;   // Q loader

    // Stage Q tile once, d-major, pre-scaled by 1/sqrt(64)
    {
        const float4* qp = (const float4*)(g_q + ((size_t)bh*SEQ + q0 + qr)*HDIM + qc);
        #pragma unroll
        for (int u = 0; u < 8; u++) {
            float4 v = qp[u];
            QS(qc+4*u+0, qr) = v.x*0.125f; QS(qc+4*u+1, qr) = v.y*0.125f;
            QS(qc+4*u+2, qr) = v.z*0.125f; QS(qc+4*u+3, qr) = v.w*0.125f;
        }
    }

    float m_i[8], l_i[8], acc[8][4];
    #pragma unroll
    for (int i = 0; i < 8; i++) {
        m_i[i] = -INFINITY; l_i[i] = 0.f;
        #pragma unroll
        for (int j = 0; j < 4; j++) acc[i][j] = 0.f;
    }

    for (int kt = 0; kt < SEQ/64; kt++) {
        const float4* kp = (const float4*)(g_k + ((size_t)bh*SEQ + kt*64 + lr)*HDIM + lc);
        const float4* vp = (const float4*)(g_v + ((size_t)bh*SEQ + kt*64 + lr)*HDIM + lc);
        __syncthreads();                 // prev iter's readers of KS/VS/PS done
        #pragma unroll
        for (int u = 0; u < 4; u++) {
            float4 kv = kp[u];
            KS(lc+4*u+0, lr) = kv.x; KS(lc+4*u+1, lr) = kv.y;
            KS(lc+4*u+2, lr) = kv.z; KS(lc+4*u+3, lr) = kv.w;
            *(float4*)&VS(lr, lc+4*u) = vp[u];
        }
        __syncthreads();                 // tiles visible (also covers Q on kt=0)

        // S = Q K^T (8x4 per thread), rank-1 updates over d
        float s[8][4] = {};
        #pragma unroll 8
        for (int d = 0; d < 64; d++) {
            float4 q0v = *(const float4*)&QS(d, ty*8);
            float4 q1v = *(const float4*)&QS(d, ty*8+4);
            float4 kv  = *(const float4*)&KS(d, tx*4);
            float qr8[8] = {q0v.x,q0v.y,q0v.z,q0v.w, q1v.x,q1v.y,q1v.z,q1v.w};
            float kr4[4] = {kv.x, kv.y, kv.z, kv.w};
            #pragma unroll
            for (int i = 0; i < 8; i++)
                #pragma unroll
                for (int j = 0; j < 4; j++)
                    s[i][j] += qr8[i] * kr4[j];
        }

        // online softmax per query row (reduce over 16 tx lanes, in-warp)
        #pragma unroll
        for (int i = 0; i < 8; i++) {
            float mt = fmaxf(fmaxf(s[i][0], s[i][1]), fmaxf(s[i][2], s[i][3]));
            mt = fmaxf(mt, __shfl_xor_sync(0xffffffffu, mt, 1));
            mt = fmaxf(mt, __shfl_xor_sync(0xffffffffu, mt, 2));
            mt = fmaxf(mt, __shfl_xor_sync(0xffffffffu, mt, 4));
            mt = fmaxf(mt, __shfl_xor_sync(0xffffffffu, mt, 8));
            float mnew  = fmaxf(m_i[i], mt);
            float scale = __expf(m_i[i] - mnew);     // first tile: exp(-inf)=0
            float ls = 0.f;
            #pragma unroll
            for (int j = 0; j < 4; j++) {
                float p = __expf(s[i][j] - mnew);
                s[i][j] = p; ls += p;
            }
            ls += __shfl_xor_sync(0xffffffffu, ls, 1);
            ls += __shfl_xor_sync(0xffffffffu, ls, 2);
            ls += __shfl_xor_sync(0xffffffffu, ls, 4);
            ls += __shfl_xor_sync(0xffffffffu, ls, 8);
            l_i[i] = l_i[i]*scale + ls;
            m_i[i] = mnew;
            #pragma unroll
            for (int j = 0; j < 4; j++) acc[i][j] *= scale;
        }

        // publish P^T[j][m] into its dedicated buffer
        #pragma unroll
        for (int i = 0; i < 8; i++)
            #pragma unroll
            for (int j = 0; j < 4; j++)
                PS(tx*4 + j, ty*8 + i) = s[i][j];
        __syncthreads();                 // P visible to all warps

        // O += P V (8x4 per thread), rank-1 updates over key index j
        #pragma unroll 8
        for (int j = 0; j < 64; j++) {
            float4 p0 = *(const float4*)&PS(j, ty*8);
            float4 p1 = *(const float4*)&PS(j, ty*8+4);
            float4 vv = *(const float4*)&VS(j, tx*4);
            float pr8[8] = {p0.x,p0.y,p0.z,p0.w, p1.x,p1.y,p1.z,p1.w};
            float vr4[4] = {vv.x, vv.y, vv.z, vv.w};
            #pragma unroll
            for (int i = 0; i < 8; i++)
                #pragma unroll
                for (int jj = 0; jj < 4; jj++)
                    acc[i][jj] += pr8[i] * vr4[jj];
        }
    }

    const int b = bh / NHEAD, h = bh % NHEAD;
    #pragma unroll
    for (int i = 0; i < 8; i++) {
        float inv = 1.0f / l_i[i];
        float4 o;
        o.x = acc[i][0]*inv; o.y = acc[i][1]*inv;
        o.z = acc[i][2]*inv; o.w = acc[i][3]*inv;
        *(float4*)(g_attn + ((size_t)(b*SEQ) + q0 + ty*8 + i)*DMODEL + h*HDIM + tx*4) = o;
    }
}

// ---------------------------------------------------------------------------
extern "C" void kernel_launch(void* const* d_in, const int* in_sizes, int n_in,
                              void* d_out, int out_size)
{
    const float* x   = (const float*)d_in[0];
    const float* qw  = (const float*)d_in[1];
    const float* qb  = (const float*)d_in[2];
    const float* kw  = (const float*)d_in[3];
    const float* kb  = (const float*)d_in[4];
    const float* vw  = (const float*)d_in[5];
    const float* vb  = (const float*)d_in[6];
    const float* ow  = (const float*)d_in[7];
    const float* ob  = (const float*)d_in[8];
    float* out = (float*)d_out;

    cudaFuncSetAttribute(attn_kernel,
                         cudaFuncAttributeMaxDynamicSharedMemorySize, ATTN_SMEM);

    dim3 gg(DMODEL/64, M_ROWS/128);          // (12, 64)
    gemm_kernel<0><<<gg, 256>>>(x, qw, qb, nullptr, 0);
    gemm_kernel<0><<<gg, 256>>>(x, kw, kb, nullptr, 1);
    gemm_kernel<0><<<gg, 256>>>(x, vw, vb, nullptr, 2);

    attn_kernel<<<dim3(SEQ/128, BATCH*NHEAD), 256, ATTN_SMEM>>>();

    // A operand resolved inside the kernel (MODE 1) — never pass a
    // __device__ symbol from host code.
    gemm_kernel<1><<<gg, 256>>>(nullptr, ow, ob, out, 0);
}

// round 15
// speedup vs baseline: 1.7325x; 1.7325x over previous
#include <cuda_runtime.h>
#include <cuda_bf16.h>
#include <math.h>
#include <stdint.h>

#define BATCH 4
#define SEQ 2048
#define DMODEL 768
#define NHEAD 12
#define HDIM 64
#define M_ROWS (BATCH*SEQ)   // 8192

// Scratch (device globals: allocation is forbidden)
__device__ float g_q[(size_t)BATCH*NHEAD*SEQ*HDIM];
__device__ float g_k[(size_t)BATCH*NHEAD*SEQ*HDIM];
__device__ float g_v[(size_t)BATCH*NHEAD*SEQ*HDIM];
__device__ float g_attn[(size_t)M_ROWS*DMODEL];

// ===========================================================================
// Split-bf16 GEMM via mma.sync (HMMA — supported on plain sm_103 target).
// C[m,n] = sum_k A[m,k]*W[n,k] + bias[n].
// Tile M=128 x N=64, K chunks of 64. 8 warps, warp tile 32x32 (2x4 fragments
// of m16n8k16, 3 split passes: AhiBhi + AhiBlo + AloBhi, fp32 accum).
// Shared: K-major bf16, row stride 88 bf16 (176B -> conflict-free LDS.32
// fragment loads: bank = row*44 + tid4 mod 32, all distinct; 16B-aligned
// stores since 176 % 16 == 0).
// MODE 0: A = x, scatter [b,h,s,hd] (sel 0/1/2 -> q/k/v). MODE 1: A = g_attn
// (device symbol resolved in device code), output row-major to Cq.
// ===========================================================================
#define GSTRIDE 176                    // bytes per 64-col bf16 row (88 bf16)
#define OFF_AHI  0
#define OFF_ALO  (128*GSTRIDE)         // 22528
#define OFF_BHI  (2*128*GSTRIDE)       // 45056
#define OFF_BLO  (2*128*GSTRIDE + 64*GSTRIDE)
#define GK_SMEM  (2*128*GSTRIDE + 2*64*GSTRIDE)   // 67584 B

__device__ __forceinline__ uint32_t pk_bf2(__nv_bfloat16 a, __nv_bfloat16 b) {
    __nv_bfloat162 t(a, b);
    return *(uint32_t*)&t;
}

// convert 8 floats -> hi/lo bf16, store 16B each at (row, col..col+7), col%8==0
__device__ __forceinline__ void cvt_store8(char* smbase, int hi_off, int lo_off,
                                           int row, int col, float4 v0, float4 v1)
{
    float f[8] = {v0.x, v0.y, v0.z, v0.w, v1.x, v1.y, v1.z, v1.w};
    __nv_bfloat16 h[8]; __nv_bfloat16 l[8];
    #pragma unroll
    for (int i = 0; i < 8; i++) {
        h[i] = __float2bfloat16(f[i]);
        l[i] = __float2bfloat16(f[i] - __bfloat162float(h[i]));
    }
    uint32_t off = (uint32_t)(row * GSTRIDE + col * 2);
    uint4 ph = make_uint4(pk_bf2(h[0],h[1]), pk_bf2(h[2],h[3]), pk_bf2(h[4],h[5]), pk_bf2(h[6],h[7]));
    uint4 pl = make_uint4(pk_bf2(l[0],l[1]), pk_bf2(l[2],l[3]), pk_bf2(l[4],l[5]), pk_bf2(l[6],l[7]));
    *(uint4*)(smbase + hi_off + off) = ph;
    *(uint4*)(smbase + lo_off + off) = pl;
}

__device__ __forceinline__ void mma_bf16(float* d, const uint32_t* a, const uint32_t* b)
{
    asm volatile(
        "mma.sync.aligned.m16n8k16.row.col.f32.bf16.bf16.f32 "
        "{%0,%1,%2,%3}, {%4,%5,%6,%7}, {%8,%9}, {%0,%1,%2,%3};"
        : "+f"(d[0]), "+f"(d[1]), "+f"(d[2]), "+f"(d[3])
        : "r"(a[0]), "r"(a[1]), "r"(a[2]), "r"(a[3]), "r"(b[0]), "r"(b[1]));
}

// A fragment (m16k16, row-major): a0={A[g][k0+t2],..}, a1 row+8, a2 k+8, a3 both
__device__ __forceinline__ void ldfrag_a(uint32_t* a, const char* base, int off,
                                         int rb, int kb, int gid, int tid4)
{
    const char* p = base + off + (rb + gid) * GSTRIDE + (kb + tid4*2) * 2;
    a[0] = *(const uint32_t*)(p);
    a[1] = *(const uint32_t*)(p + 8*GSTRIDE);
    a[2] = *(const uint32_t*)(p + 16);
    a[3] = *(const uint32_t*)(p + 8*GSTRIDE + 16);
}
// B fragment (k16n8, W stored [n][k] K-major): b0={W[n][k0+t2],..}, b1 k+8
__device__ __forceinline__ void ldfrag_b(uint32_t* b, const char* base, int off,
                                         int nb, int kb, int gid, int tid4)
{
    const char* p = base + off + (nb + gid) * GSTRIDE + (kb + tid4*2) * 2;
    b[0] = *(const uint32_t*)(p);
    b[1] = *(const uint32_t*)(p + 16);
}

template<int MODE>
__global__ void __launch_bounds__(256) mma_gemm_kernel(const float* __restrict__ A,
                                                       const float* __restrict__ W,
                                                       const float* __restrict__ bias,
                                                       float* __restrict__ Cq, int sel)
{
    extern __shared__ __align__(16) char smg[];
    const int tid = threadIdx.x;
    const int wid = tid >> 5, lane = tid & 31;
    const int gid = lane >> 2, tid4 = lane & 3;
    const int wr = wid & 3, wc = wid >> 2;          // warp tile: (wr*32 M, wc*32 N)
    const int m0 = blockIdx.y * 128, n0 = blockIdx.x * 64;

    const float* Asrc = (MODE == 1) ? (const float*)g_attn : A;
    const int arow = tid >> 1, acol = (tid & 1) * 32;   // A loader: 2 thr/row, 32 cols
    const int brow = tid >> 2, bcol = (tid & 3) * 16;   // B loader: 4 thr/row, 16 cols
    const float4* Ap = (const float4*)(Asrc + (size_t)(m0 + arow) * DMODEL + acol);
    const float4* Bp = (const float4*)(W    + (size_t)(n0 + brow) * DMODEL + bcol);

    float acc[2][4][4] = {};   // [mi][ni][reg]

    for (int c = 0; c < 12; c++) {
        // prefetch chunk c globals (overlaps chunk c-1 MMA below the barrier)
        float4 av[8], bv[4];
        #pragma unroll
        for (int u = 0; u < 8; u++) av[u] = Ap[c*16 + u];
        #pragma unroll
        for (int u = 0; u < 4; u++) bv[u] = Bp[c*16 + u];

        __syncthreads();       // prev chunk's fragment readers done
        #pragma unroll
        for (int g = 0; g < 4; g++)
            cvt_store8(smg, OFF_AHI, OFF_ALO, arow, acol + g*8, av[g*2], av[g*2+1]);
        #pragma unroll
        for (int g = 0; g < 2; g++)
            cvt_store8(smg, OFF_BHI, OFF_BLO, brow, bcol + g*8, bv[g*2], bv[g*2+1]);
        __syncthreads();       // tiles visible

        #pragma unroll
        for (int ks = 0; ks < 4; ks++) {
            const int kb = ks * 16;
            uint32_t ahi[2][4], alo[2][4], bhi[4][2], blo[4][2];
            #pragma unroll
            for (int mi = 0; mi < 2; mi++) {
                ldfrag_a(ahi[mi], smg, OFF_AHI, wr*32 + mi*16, kb, gid, tid4);
                ldfrag_a(alo[mi], smg, OFF_ALO, wr*32 + mi*16, kb, gid, tid4);
            }
            #pragma unroll
            for (int ni = 0; ni < 4; ni++) {
                ldfrag_b(bhi[ni], smg, OFF_BHI, wc*32 + ni*8, kb, gid, tid4);
                ldfrag_b(blo[ni], smg, OFF_BLO, wc*32 + ni*8, kb, gid, tid4);
            }
            #pragma unroll
            for (int mi = 0; mi < 2; mi++)
                #pragma unroll
                for (int ni = 0; ni < 4; ni++) {
                    mma_bf16(acc[mi][ni], ahi[mi], bhi[ni]);
                    mma_bf16(acc[mi][ni], ahi[mi], blo[ni]);
                    mma_bf16(acc[mi][ni], alo[mi], bhi[ni]);
                }
        }
    }

    // Epilogue: D frag rows = gid / gid+8, cols = tid4*2, tid4*2+1
    float* outp = Cq;
    if (MODE == 0) outp = (sel == 0) ? g_q : (sel == 1) ? g_k : g_v;
    const int h = n0 >> 6;
    #pragma unroll
    for (int mi = 0; mi < 2; mi++) {
        #pragma unroll
        for (int rr = 0; rr < 2; rr++) {
            const int m = m0 + wr*32 + mi*16 + gid + rr*8;
            #pragma unroll
            for (int ni = 0; ni < 4; ni++) {
                const int cb = n0 + wc*32 + ni*8 + tid4*2;
                float2 bb = *(const float2*)(bias + cb);
                float2 o;
                o.x = acc[mi][ni][rr*2 + 0] + bb.x;
                o.y = acc[mi][ni][rr*2 + 1] + bb.y;
                if (MODE == 0) {
                    const int b = m >> 11, s = m & 2047;
                    *(float2*)(outp + (((size_t)(b*NHEAD + h))*SEQ + s)*HDIM + (cb & 63)) = o;
                } else {
                    *(float2*)(outp + (size_t)m*DMODEL + cb) = o;
                }
            }
        }
    }
}

// ---------------------------------------------------------------------------
// Flash attention — EXACT R12 version (1713us measured). grid (SEQ/64, B*H),
// 256 threads; thread owns 4x4 of the 64x64 score/output tiles. Q/K d-major,
// P^T reuses the K buffer between full barriers, V row-major.
// Dynamic shared: Qs[64][68] | KPs[64][68] | Vs[64][68]  (51 KB).
// ---------------------------------------------------------------------------
#define QS(d,m)  sm[(d)*68 + (m)]
#define KS(d,n)  sm[4352 + (d)*68 + (n)]
#define VS(j,e)  sm[8704 + (j)*68 + (e)]
#define ATTN_SMEM (3*64*68*4)

__global__ void __launch_bounds__(256, 2) attn_kernel()
{
    extern __shared__ __align__(16) float sm[];

    const int tid = threadIdx.x;
    const int tx  = tid & 15, ty = tid >> 4;
    const int bh  = blockIdx.y;
    const int q0  = blockIdx.x * 64;
    const int lr  = tid >> 2, lc = (tid & 3) * 16;

    // Stage Q tile once, d-major, pre-scaled by 1/sqrt(64)
    {
        const float4* qp = (const float4*)(g_q + ((size_t)bh*SEQ + q0 + lr)*HDIM + lc);
        #pragma unroll
        for (int u = 0; u < 4; u++) {
            float4 v = qp[u];
            QS(lc+4*u+0, lr) = v.x*0.125f; QS(lc+4*u+1, lr) = v.y*0.125f;
            QS(lc+4*u+2, lr) = v.z*0.125f; QS(lc+4*u+3, lr) = v.w*0.125f;
        }
    }

    float m_i[4], l_i[4], acc[4][4];
    #pragma unroll
    for (int i = 0; i < 4; i++) {
        m_i[i] = -INFINITY; l_i[i] = 0.f;
        #pragma unroll
        for (int j = 0; j < 4; j++) acc[i][j] = 0.f;
    }

    for (int kt = 0; kt < SEQ/64; kt++) {
        const float4* kp = (const float4*)(g_k + ((size_t)bh*SEQ + kt*64 + lr)*HDIM + lc);
        const float4* vp = (const float4*)(g_v + ((size_t)bh*SEQ + kt*64 + lr)*HDIM + lc);
        __syncthreads();                 // prev tile's PV readers done
        #pragma unroll
        for (int u = 0; u < 4; u++) {
            float4 kv = kp[u];
            KS(lc+4*u+0, lr) = kv.x; KS(lc+4*u+1, lr) = kv.y;
            KS(lc+4*u+2, lr) = kv.z; KS(lc+4*u+3, lr) = kv.w;
            *(float4*)&VS(lr, lc+4*u) = vp[u];
        }
        __syncthreads();                 // tiles visible

        // S = Q K^T (4x4 per thread), rank-1 updates over d
        float s[4][4] = {};
        #pragma unroll 16
        for (int d = 0; d < 64; d++) {
            float4 qa = *(const float4*)&QS(d, ty*4);
            float4 kb = *(const float4*)&KS(d, tx*4);
            float qr[4] = {qa.x, qa.y, qa.z, qa.w};
            float kr[4] = {kb.x, kb.y, kb.z, kb.w};
            #pragma unroll
            for (int i = 0; i < 4; i++)
                #pragma unroll
                for (int j = 0; j < 4; j++)
                    s[i][j] += qr[i] * kr[j];
        }

        // online softmax per query row (reduce over 16 tx lanes)
        #pragma unroll
        for (int i = 0; i < 4; i++) {
            float mt = fmaxf(fmaxf(s[i][0], s[i][1]), fmaxf(s[i][2], s[i][3]));
            mt = fmaxf(mt, __shfl_xor_sync(0xffffffffu, mt, 1));
            mt = fmaxf(mt, __shfl_xor_sync(0xffffffffu, mt, 2));
            mt = fmaxf(mt, __shfl_xor_sync(0xffffffffu, mt, 4));
            mt = fmaxf(mt, __shfl_xor_sync(0xffffffffu, mt, 8));
            float mnew  = fmaxf(m_i[i], mt);
            float scale = __expf(m_i[i] - mnew);     // first tile: exp(-inf)=0
            float ls = 0.f;
            #pragma unroll
            for (int j = 0; j < 4; j++) {
                float p = __expf(s[i][j] - mnew);
                s[i][j] = p; ls += p;
            }
            ls += __shfl_xor_sync(0xffffffffu, ls, 1);
            ls += __shfl_xor_sync(0xffffffffu, ls, 2);
            ls += __shfl_xor_sync(0xffffffffu, ls, 4);
            ls += __shfl_xor_sync(0xffffffffu, ls, 8);
            l_i[i] = l_i[i]*scale + ls;
            m_i[i] = mnew;
            #pragma unroll
            for (int j = 0; j < 4; j++) acc[i][j] *= scale;
        }

        __syncthreads();                 // all K reads done -> reuse KS for P^T
        #pragma unroll
        for (int i = 0; i < 4; i++)
            #pragma unroll
            for (int j = 0; j < 4; j++)
                KS(tx*4 + j, ty*4 + i) = s[i][j];    // P^T[j_key][m]
        __syncthreads();                 // P visible

        // O += P V (4x4 per thread), rank-1 updates over key index j
        #pragma unroll 16
        for (int j = 0; j < 64; j++) {
            float4 pa = *(const float4*)&KS(j, ty*4);
            float4 vb = *(const float4*)&VS(j, tx*4);
            float pr[4] = {pa.x, pa.y, pa.z, pa.w};
            float vr[4] = {vb.x, vb.y, vb.z, vb.w};
            #pragma unroll
            for (int i = 0; i < 4; i++)
                #pragma unroll
                for (int jj = 0; jj < 4; jj++)
                    acc[i][jj] += pr[i] * vr[jj];
        }
    }

    const int b = bh / NHEAD, h = bh % NHEAD;
    #pragma unroll
    for (int i = 0; i < 4; i++) {
        float inv = 1.0f / l_i[i];
        float4 o;
        o.x = acc[i][0]*inv; o.y = acc[i][1]*inv;
        o.z = acc[i][2]*inv; o.w = acc[i][3]*inv;
        *(float4*)(g_attn + ((size_t)(b*SEQ) + q0 + ty*4 + i)*DMODEL + h*HDIM + tx*4) = o;
    }
}

// ---------------------------------------------------------------------------
extern "C" void kernel_launch(void* const* d_in, const int* in_sizes, int n_in,
                              void* d_out, int out_size)
{
    const float* x   = (const float*)d_in[0];
    const float* qw  = (const float*)d_in[1];
    const float* qb  = (const float*)d_in[2];
    const float* kw  = (const float*)d_in[3];
    const float* kb  = (const float*)d_in[4];
    const float* vw  = (const float*)d_in[5];
    const float* vb  = (const float*)d_in[6];
    const float* ow  = (const float*)d_in[7];
    const float* ob  = (const float*)d_in[8];
    float* out = (float*)d_out;

    cudaFuncSetAttribute(attn_kernel,
                         cudaFuncAttributeMaxDynamicSharedMemorySize, ATTN_SMEM);
    cudaFuncSetAttribute(mma_gemm_kernel<0>,
                         cudaFuncAttributeMaxDynamicSharedMemorySize, GK_SMEM);
    cudaFuncSetAttribute(mma_gemm_kernel<1>,
                         cudaFuncAttributeMaxDynamicSharedMemorySize, GK_SMEM);

    dim3 gg(DMODEL/64, M_ROWS/128);          // (12, 64)
    mma_gemm_kernel<0><<<gg, 256, GK_SMEM>>>(x, qw, qb, nullptr, 0);
    mma_gemm_kernel<0><<<gg, 256, GK_SMEM>>>(x, kw, kb, nullptr, 1);
    mma_gemm_kernel<0><<<gg, 256, GK_SMEM>>>(x, vw, vb, nullptr, 2);

    attn_kernel<<<dim3(SEQ/64, BATCH*NHEAD), 256, ATTN_SMEM>>>();

    // A operand resolved inside the kernel (MODE 1) — never pass a
    // __device__ symbol from host code.
    mma_gemm_kernel<1><<<gg, 256, GK_SMEM>>>(nullptr, ow, ob, out, 0);
}

// round 16
// speedup vs baseline: 3.1047x; 1.7920x over previous
#include <cuda_runtime.h>
#include <cuda_bf16.h>
#include <math.h>
#include <stdint.h>

#define BATCH 4
#define SEQ 2048
#define DMODEL 768
#define NHEAD 12
#define HDIM 64
#define M_ROWS (BATCH*SEQ)   // 8192

// Scratch (device globals: allocation is forbidden)
__device__ float g_q[(size_t)BATCH*NHEAD*SEQ*HDIM];
__device__ float g_k[(size_t)BATCH*NHEAD*SEQ*HDIM];
__device__ float g_v[(size_t)BATCH*NHEAD*SEQ*HDIM];
__device__ float g_attn[(size_t)M_ROWS*DMODEL];

// ===========================================================================
// Shared HMMA utilities (fragment layouts verified by the R15 GEMM pass)
// ===========================================================================
#define GSTRIDE 176                    // bytes per 64-col bf16 row (88 bf16)

__device__ __forceinline__ uint32_t pk_bf2(__nv_bfloat16 a, __nv_bfloat16 b) {
    __nv_bfloat162 t(a, b);
    return *(uint32_t*)&t;
}

// convert 8 floats -> hi/lo bf16 (optionally pre-scaled), store 16B each
__device__ __forceinline__ void cvt_store8(char* smbase, int hi_off, int lo_off,
                                           int row, int col, float4 v0, float4 v1,
                                           float scale)
{
    float f[8] = {v0.x*scale, v0.y*scale, v0.z*scale, v0.w*scale,
                  v1.x*scale, v1.y*scale, v1.z*scale, v1.w*scale};
    __nv_bfloat16 h[8]; __nv_bfloat16 l[8];
    #pragma unroll
    for (int i = 0; i < 8; i++) {
        h[i] = __float2bfloat16(f[i]);
        l[i] = __float2bfloat16(f[i] - __bfloat162float(h[i]));
    }
    uint32_t off = (uint32_t)(row * GSTRIDE + col * 2);
    uint4 ph = make_uint4(pk_bf2(h[0],h[1]), pk_bf2(h[2],h[3]), pk_bf2(h[4],h[5]), pk_bf2(h[6],h[7]));
    uint4 pl = make_uint4(pk_bf2(l[0],l[1]), pk_bf2(l[2],l[3]), pk_bf2(l[4],l[5]), pk_bf2(l[6],l[7]));
    *(uint4*)(smbase + hi_off + off) = ph;
    *(uint4*)(smbase + lo_off + off) = pl;
}

__device__ __forceinline__ void mma_bf16(float* d, const uint32_t* a, const uint32_t* b)
{
    asm volatile(
        "mma.sync.aligned.m16n8k16.row.col.f32.bf16.bf16.f32 "
        "{%0,%1,%2,%3}, {%4,%5,%6,%7}, {%8,%9}, {%0,%1,%2,%3};"
        : "+f"(d[0]), "+f"(d[1]), "+f"(d[2]), "+f"(d[3])
        : "r"(a[0]), "r"(a[1]), "r"(a[2]), "r"(a[3]), "r"(b[0]), "r"(b[1]));
}

// A fragment (m16k16, row-major [m][k] in shared)
__device__ __forceinline__ void ldfrag_a(uint32_t* a, const char* base, int off,
                                         int rb, int kb, int gid, int tid4)
{
    const char* p = base + off + (rb + gid) * GSTRIDE + (kb + tid4*2) * 2;
    a[0] = *(const uint32_t*)(p);
    a[1] = *(const uint32_t*)(p + 8*GSTRIDE);
    a[2] = *(const uint32_t*)(p + 16);
    a[3] = *(const uint32_t*)(p + 8*GSTRIDE + 16);
}
// B fragment (k16n8, "col" = stored [n][k] k-contiguous in shared)
__device__ __forceinline__ void ldfrag_b(uint32_t* b, const char* base, int off,
                                         int nb, int kb, int gid, int tid4)
{
    const char* p = base + off + (nb + gid) * GSTRIDE + (kb + tid4*2) * 2;
    b[0] = *(const uint32_t*)(p);
    b[1] = *(const uint32_t*)(p + 16);
}

// ===========================================================================
// Split-bf16 GEMM (EXACT R15 version — measured 4.1e-6 rel_err in-graph)
// ===========================================================================
#define OFF_AHI  0
#define OFF_ALO  (128*GSTRIDE)
#define OFF_BHI  (2*128*GSTRIDE)
#define OFF_BLO  (2*128*GSTRIDE + 64*GSTRIDE)
#define GK_SMEM  (2*128*GSTRIDE + 2*64*GSTRIDE)   // 67584 B

template<int MODE>
__global__ void __launch_bounds__(256) mma_gemm_kernel(const float* __restrict__ A,
                                                       const float* __restrict__ W,
                                                       const float* __restrict__ bias,
                                                       float* __restrict__ Cq, int sel)
{
    extern __shared__ __align__(16) char smg[];
    const int tid = threadIdx.x;
    const int wid = tid >> 5, lane = tid & 31;
    const int gid = lane >> 2, tid4 = lane & 3;
    const int wr = wid & 3, wc = wid >> 2;
    const int m0 = blockIdx.y * 128, n0 = blockIdx.x * 64;

    const float* Asrc = (MODE == 1) ? (const float*)g_attn : A;
    const int arow = tid >> 1, acol = (tid & 1) * 32;
    const int brow = tid >> 2, bcol = (tid & 3) * 16;
    const float4* Ap = (const float4*)(Asrc + (size_t)(m0 + arow) * DMODEL + acol);
    const float4* Bp = (const float4*)(W    + (size_t)(n0 + brow) * DMODEL + bcol);

    float acc[2][4][4] = {};

    for (int c = 0; c < 12; c++) {
        float4 av[8], bv[4];
        #pragma unroll
        for (int u = 0; u < 8; u++) av[u] = Ap[c*16 + u];
        #pragma unroll
        for (int u = 0; u < 4; u++) bv[u] = Bp[c*16 + u];

        __syncthreads();
        #pragma unroll
        for (int g = 0; g < 4; g++)
            cvt_store8(smg, OFF_AHI, OFF_ALO, arow, acol + g*8, av[g*2], av[g*2+1], 1.f);
        #pragma unroll
        for (int g = 0; g < 2; g++)
            cvt_store8(smg, OFF_BHI, OFF_BLO, brow, bcol + g*8, bv[g*2], bv[g*2+1], 1.f);
        __syncthreads();

        #pragma unroll
        for (int ks = 0; ks < 4; ks++) {
            const int kb = ks * 16;
            uint32_t ahi[2][4], alo[2][4], bhi[4][2], blo[4][2];
            #pragma unroll
            for (int mi = 0; mi < 2; mi++) {
                ldfrag_a(ahi[mi], smg, OFF_AHI, wr*32 + mi*16, kb, gid, tid4);
                ldfrag_a(alo[mi], smg, OFF_ALO, wr*32 + mi*16, kb, gid, tid4);
            }
            #pragma unroll
            for (int ni = 0; ni < 4; ni++) {
                ldfrag_b(bhi[ni], smg, OFF_BHI, wc*32 + ni*8, kb, gid, tid4);
                ldfrag_b(blo[ni], smg, OFF_BLO, wc*32 + ni*8, kb, gid, tid4);
            }
            #pragma unroll
            for (int mi = 0; mi < 2; mi++)
                #pragma unroll
                for (int ni = 0; ni < 4; ni++) {
                    mma_bf16(acc[mi][ni], ahi[mi], bhi[ni]);
                    mma_bf16(acc[mi][ni], ahi[mi], blo[ni]);
                    mma_bf16(acc[mi][ni], alo[mi], bhi[ni]);
                }
        }
    }

    float* outp = Cq;
    if (MODE == 0) outp = (sel == 0) ? g_q : (sel == 1) ? g_k : g_v;
    const int h = n0 >> 6;
    #pragma unroll
    for (int mi = 0; mi < 2; mi++) {
        #pragma unroll
        for (int rr = 0; rr < 2; rr++) {
            const int m = m0 + wr*32 + mi*16 + gid + rr*8;
            #pragma unroll
            for (int ni = 0; ni < 4; ni++) {
                const int cb = n0 + wc*32 + ni*8 + tid4*2;
                float2 bb = *(const float2*)(bias + cb);
                float2 o;
                o.x = acc[mi][ni][rr*2 + 0] + bb.x;
                o.y = acc[mi][ni][rr*2 + 1] + bb.y;
                if (MODE == 0) {
                    const int b = m >> 11, s = m & 2047;
                    *(float2*)(outp + (((size_t)(b*NHEAD + h))*SEQ + s)*HDIM + (cb & 63)) = o;
                } else {
                    *(float2*)(outp + (size_t)m*DMODEL + cb) = o;
                }
            }
        }
    }
}

// ===========================================================================
// Flash attention via split-bf16 HMMA.
// Q-tile 128, K-tile 64. grid (SEQ/128, B*H), 256 thr = 8 warps; warp w owns
// q-rows [w*16, w*16+16) (full 64-key rows -> softmax stays in-warp).
// QK^T: Q hi/lo (1/8 folded in) x K hi/lo, 3 passes, fp32 accum.
// P: repacked in REGISTERS from D frags to A frags (rows gid/gid+8 match,
// cols tid4*2+8*ni map to k of step ks=ni/2), split hi/lo.
// PV: V stored TRANSPOSED in shared (VT[d][key], hi/lo) as the col-B operand.
// Shared: Qhi|Qlo (128x176) Khi|Klo (64x176) VThi|VTlo (64x176) = 88 KB.
// ===========================================================================
#define AQHI 0
#define AQLO (128*GSTRIDE)
#define AKHI (2*128*GSTRIDE)
#define AKLO (2*128*GSTRIDE + 64*GSTRIDE)
#define AVHI (2*128*GSTRIDE + 2*64*GSTRIDE)
#define AVLO (2*128*GSTRIDE + 3*64*GSTRIDE)
#define ATTN_SMEM (2*128*GSTRIDE + 4*64*GSTRIDE)   // 90112 B

__global__ void __launch_bounds__(256, 2) attn_kernel()
{
    extern __shared__ __align__(16) char smA[];

    const int tid  = threadIdx.x;
    const int wid  = tid >> 5, lane = tid & 31;
    const int gid  = lane >> 2, tid4 = lane & 3;
    const int bh   = blockIdx.y;
    const int q0   = blockIdx.x * 128;

    // ---- stage Q (128 x 64) hi/lo, scale 1/8 folded in ----
    {
        const int qrow = tid >> 1, qcol = (tid & 1) * 32;
        const float4* qp = (const float4*)(g_q + ((size_t)bh*SEQ + q0 + qrow)*HDIM + qcol);
        float4 qv[8];
        #pragma unroll
        for (int u = 0; u < 8; u++) qv[u] = qp[u];
        #pragma unroll
        for (int g = 0; g < 4; g++)
            cvt_store8(smA, AQHI, AQLO, qrow, qcol + g*8, qv[g*2], qv[g*2+1], 0.125f);
    }

    float m_i[2] = {-INFINITY, -INFINITY}, l_i[2] = {0.f, 0.f};
    float o[8][4] = {};

    const int krow = tid >> 2, kcol = (tid & 3) * 16;  // K loader
    const int rp = tid >> 3, dg = (tid & 7) * 8;       // V transposer: key pair, dim grp

    for (int kt = 0; kt < SEQ/64; kt++) {
        // prefetch K and V tiles
        const float4* kp = (const float4*)(g_k + ((size_t)bh*SEQ + kt*64 + krow)*HDIM + kcol);
        float4 kv[4];
        #pragma unroll
        for (int u = 0; u < 4; u++) kv[u] = kp[u];
        const float* v0p = g_v + ((size_t)bh*SEQ + kt*64 + 2*rp)*HDIM + dg;
        float4 v0a = *(const float4*)(v0p),      v0b = *(const float4*)(v0p + 4);
        float4 v1a = *(const float4*)(v0p+HDIM), v1b = *(const float4*)(v0p + HDIM + 4);

        __syncthreads();   // prev iteration's K/V readers done (kt=0: Q stores ordered too)
        #pragma unroll
        for (int g = 0; g < 2; g++)
            cvt_store8(smA, AKHI, AKLO, krow, kcol + g*8, kv[g*2], kv[g*2+1], 1.f);
        // V transpose: VT[d][key], pack key pair (2rp, 2rp+1); bank-staggered order
        {
            float r0[8] = {v0a.x,v0a.y,v0a.z,v0a.w, v0b.x,v0b.y,v0b.z,v0b.w};
            float r1[8] = {v1a.x,v1a.y,v1a.z,v1a.w, v1b.x,v1b.y,v1b.z,v1b.w};
            #pragma unroll
            for (int i = 0; i < 8; i++) {
                const int ii = (i + (tid & 7)) & 7;
                const int d  = dg + ii;
                __nv_bfloat16 h0 = __float2bfloat16(r0[ii]);
                __nv_bfloat16 h1 = __float2bfloat16(r1[ii]);
                __nv_bfloat16 l0 = __float2bfloat16(r0[ii] - __bfloat162float(h0));
                __nv_bfloat16 l1 = __float2bfloat16(r1[ii] - __bfloat162float(h1));
                *(uint32_t*)(smA + AVHI + d*GSTRIDE + rp*4) = pk_bf2(h0, h1);
                *(uint32_t*)(smA + AVLO + d*GSTRIDE + rp*4) = pk_bf2(l0, l1);
            }
        }
        __syncthreads();   // tiles visible

        // ---- S = Q K^T : warp rows wid*16, 8 key tiles, 4 d-steps, 3 passes
        float s[8][4] = {};
        #pragma unroll
        for (int ks = 0; ks < 4; ks++) {
            uint32_t qh[4], ql[4];
            ldfrag_a(qh, smA, AQHI, wid*16, ks*16, gid, tid4);
            ldfrag_a(ql, smA, AQLO, wid*16, ks*16, gid, tid4);
            #pragma unroll
            for (int ni = 0; ni < 8; ni++) {
                uint32_t kh[2], kl[2];
                ldfrag_b(kh, smA, AKHI, ni*8, ks*16, gid, tid4);
                ldfrag_b(kl, smA, AKLO, ni*8, ks*16, gid, tid4);
                mma_bf16(s[ni], qh, kh);
                mma_bf16(s[ni], qh, kl);
                mma_bf16(s[ni], ql, kh);
            }
        }

        // ---- online softmax: rows gid (half 0) / gid+8 (half 1); cols span
        //      the 16 values held across this thread + its tid4 quad-mates
        #pragma unroll
        for (int hf = 0; hf < 2; hf++) {
            float mt = -INFINITY;
            #pragma unroll
            for (int ni = 0; ni < 8; ni++)
                mt = fmaxf(mt, fmaxf(s[ni][2*hf], s[ni][2*hf+1]));
            mt = fmaxf(mt, __shfl_xor_sync(0xffffffffu, mt, 1));
            mt = fmaxf(mt, __shfl_xor_sync(0xffffffffu, mt, 2));
            float mnew  = fmaxf(m_i[hf], mt);
            float scale = __expf(m_i[hf] - mnew);
            float ls = 0.f;
            #pragma unroll
            for (int ni = 0; ni < 8; ni++) {
                float p0 = __expf(s[ni][2*hf]   - mnew);
                float p1 = __expf(s[ni][2*hf+1] - mnew);
                s[ni][2*hf] = p0; s[ni][2*hf+1] = p1; ls += p0 + p1;
            }
            ls += __shfl_xor_sync(0xffffffffu, ls, 1);
            ls += __shfl_xor_sync(0xffffffffu, ls, 2);
            l_i[hf] = l_i[hf]*scale + ls;
            m_i[hf] = mnew;
            #pragma unroll
            for (int ni = 0; ni < 8; ni++) {
                o[ni][2*hf]   *= scale;
                o[ni][2*hf+1] *= scale;
            }
        }

        // ---- O += P V : P repacked from D frags to A frags in registers,
        //      split hi/lo; V^T frags from shared (col-B operand)
        #pragma unroll
        for (int ks = 0; ks < 4; ks++) {
            // A frag covers keys [16ks, 16ks+16) = score tiles 2ks, 2ks+1
            float p00 = s[2*ks][0],   p01 = s[2*ks][1];
            float p02 = s[2*ks][2],   p03 = s[2*ks][3];
            float p10 = s[2*ks+1][0], p11 = s[2*ks+1][1];
            float p12 = s[2*ks+1][2], p13 = s[2*ks+1][3];
            __nv_bfloat16 h00=__float2bfloat16(p00), h01=__float2bfloat16(p01);
            __nv_bfloat16 h02=__float2bfloat16(p02), h03=__float2bfloat16(p03);
            __nv_bfloat16 h10=__float2bfloat16(p10), h11=__float2bfloat16(p11);
            __nv_bfloat16 h12=__float2bfloat16(p12), h13=__float2bfloat16(p13);
            uint32_t ph[4], pl[4];
            ph[0] = pk_bf2(h00, h01);  ph[1] = pk_bf2(h02, h03);
            ph[2] = pk_bf2(h10, h11);  ph[3] = pk_bf2(h12, h13);
            pl[0] = pk_bf2(__float2bfloat16(p00-__bfloat162float(h00)),
                           __float2bfloat16(p01-__bfloat162float(h01)));
            pl[1] = pk_bf2(__float2bfloat16(p02-__bfloat162float(h02)),
                           __float2bfloat16(p03-__bfloat162float(h03)));
            pl[2] = pk_bf2(__float2bfloat16(p10-__bfloat162float(h10)),
                           __float2bfloat16(p11-__bfloat162float(h11)));
            pl[3] = pk_bf2(__float2bfloat16(p12-__bfloat162float(h12)),
                           __float2bfloat16(p13-__bfloat162float(h13)));
            #pragma unroll
            for (int ni = 0; ni < 8; ni++) {
                uint32_t vh[2], vl[2];
                ldfrag_b(vh, smA, AVHI, ni*8, ks*16, gid, tid4);
                ldfrag_b(vl, smA, AVLO, ni*8, ks*16, gid, tid4);
                mma_bf16(o[ni], ph, vh);
                mma_bf16(o[ni], ph, vl);
                mma_bf16(o[ni], pl, vh);
            }
        }
    }

    // ---- epilogue ----
    const int b = bh / NHEAD, hh = bh % NHEAD;
    float inv0 = 1.0f / l_i[0], inv1 = 1.0f / l_i[1];
    #pragma unroll
    for (int hf = 0; hf < 2; hf++) {
        const int r = q0 + wid*16 + gid + 8*hf;
        const float inv = hf ? inv1 : inv0;
        float* dst = g_attn + ((size_t)(b*SEQ) + r)*DMODEL + hh*HDIM + tid4*2;
        #pragma unroll
        for (int ni = 0; ni < 8; ni++) {
            float2 ov;
            ov.x = o[ni][2*hf]   * inv;
            ov.y = o[ni][2*hf+1] * inv;
            *(float2*)(dst + ni*8) = ov;
        }
    }
}

// ---------------------------------------------------------------------------
extern "C" void kernel_launch(void* const* d_in, const int* in_sizes, int n_in,
                              void* d_out, int out_size)
{
    const float* x   = (const float*)d_in[0];
    const float* qw  = (const float*)d_in[1];
    const float* qb  = (const float*)d_in[2];
    const float* kw  = (const float*)d_in[3];
    const float* kb  = (const float*)d_in[4];
    const float* vw  = (const float*)d_in[5];
    const float* vb  = (const float*)d_in[6];
    const float* ow  = (const float*)d_in[7];
    const float* ob  = (const float*)d_in[8];
    float* out = (float*)d_out;

    cudaFuncSetAttribute(attn_kernel,
                         cudaFuncAttributeMaxDynamicSharedMemorySize, ATTN_SMEM);
    cudaFuncSetAttribute(mma_gemm_kernel<0>,
                         cudaFuncAttributeMaxDynamicSharedMemorySize, GK_SMEM);
    cudaFuncSetAttribute(mma_gemm_kernel<1>,
                         cudaFuncAttributeMaxDynamicSharedMemorySize, GK_SMEM);

    dim3 gg(DMODEL/64, M_ROWS/128);          // (12, 64)
    mma_gemm_kernel<0><<<gg, 256, GK_SMEM>>>(x, qw, qb, nullptr, 0);
    mma_gemm_kernel<0><<<gg, 256, GK_SMEM>>>(x, kw, kb, nullptr, 1);
    mma_gemm_kernel<0><<<gg, 256, GK_SMEM>>>(x, vw, vb, nullptr, 2);

    attn_kernel<<<dim3(SEQ/128, BATCH*NHEAD), 256, ATTN_SMEM>>>();

    // A operand resolved inside the kernel (MODE 1) — never pass a
    // __device__ symbol from host code.
    mma_gemm_kernel<1><<<gg, 256, GK_SMEM>>>(nullptr, ow, ob, out, 0);
}